// round 3
// baseline (speedup 1.0000x reference)
#include <cuda_runtime.h>
#include <cuda_bf16.h>
#include <math.h>

// Problem constants (fixed dataset)
#define NN 131072      // sentences
#define DD 690         // feature dim (even)
#define D2 345         // DD/2 (float2)
#define CC 53          // classes
#define BB 8192        // bags
#define NSLOT 11       // ceil(D2/32)

// Device scratch (allocation-free rule: __device__ globals)
__device__ float g_prod[CC * DD];          // att ⊙ rel, 143 KB
__device__ float g_logit[NN];              // per-sentence attention logit, 512 KB
__device__ float g_bag[(size_t)BB * DD];   // bag representations, 22.6 MB

// ---------------------------------------------------------------------------
// Kernel 0: prod[c,d] = att[c,d] * rel[c,d]
// ---------------------------------------------------------------------------
__global__ void prod_kernel(const float* __restrict__ rel,
                            const float* __restrict__ att) {
    int i = blockIdx.x * 256 + threadIdx.x;
    if (i < CC * DD) g_prod[i] = rel[i] * att[i];
}

// ---------------------------------------------------------------------------
// Kernel 1: one block per bag.
//   loop1 (warp/sentence): logit_i = x_i · prod[q_i]  -> g_logit, track max
//   loop2 (thread/sentence): denom = sum exp(logit - max)
//   loop3 (warp/sentence): bag_acc += (exp(logit-max)/denom) * x_i
// Second x read hits L2 (same block, back-to-back).
// ---------------------------------------------------------------------------
__global__ void __launch_bounds__(256)
bag_attn_kernel(const float* __restrict__ x,
                const int*   __restrict__ q,
                const int*   __restrict__ scope) {
    __shared__ float s_partial[8][DD];   // 22080 B
    __shared__ float s_red[8];
    __shared__ float s_bagmax, s_denom;

    const int b     = blockIdx.x;
    const int start = scope[b];
    const int end   = scope[b + 1];
    const int tid   = threadIdx.x;
    const int wid   = tid >> 5;
    const int lane  = tid & 31;

    const float2* __restrict__ x2 = reinterpret_cast<const float2*>(x);
    const float2* __restrict__ p2 = reinterpret_cast<const float2*>(g_prod);

    // ---- loop1: logits + warp-local max ----
    float wmax = -INFINITY;
    for (int s = start + wid; s < end; s += 8) {
        const float2* xr = x2 + (size_t)s * D2;
        const float2* pr = p2 + (size_t)q[s] * D2;
        float2 xa[NSLOT], pa[NSLOT];
        #pragma unroll
        for (int i = 0; i < NSLOT; i++) {
            int d = lane + i * 32;
            if (d < D2) { xa[i] = xr[d]; pa[i] = pr[d]; }
            else        { xa[i] = make_float2(0.f, 0.f); pa[i] = make_float2(0.f, 0.f); }
        }
        float acc = 0.f;
        #pragma unroll
        for (int i = 0; i < NSLOT; i++) {
            acc = fmaf(xa[i].x, pa[i].x, acc);
            acc = fmaf(xa[i].y, pa[i].y, acc);
        }
        #pragma unroll
        for (int off = 16; off; off >>= 1)
            acc += __shfl_xor_sync(0xFFFFFFFFu, acc, off);
        if (lane == 0) g_logit[s] = acc;
        wmax = fmaxf(wmax, acc);
    }
    if (lane == 0) s_red[wid] = wmax;
    __syncthreads();
    if (tid == 0) {
        float m = s_red[0];
        #pragma unroll
        for (int i = 1; i < 8; i++) m = fmaxf(m, s_red[i]);
        s_bagmax = m;
    }
    __syncthreads();
    const float bagmax = s_bagmax;

    // ---- loop2: denominator ----
    float lsum = 0.f;
    for (int s = start + tid; s < end; s += 256)
        lsum += expf(g_logit[s] - bagmax);
    #pragma unroll
    for (int off = 16; off; off >>= 1)
        lsum += __shfl_xor_sync(0xFFFFFFFFu, lsum, off);
    if (lane == 0) s_red[wid] = lsum;
    __syncthreads();
    if (tid == 0) {
        float t = 0.f;
        #pragma unroll
        for (int i = 0; i < 8; i++) t += s_red[i];
        s_denom = t;
    }
    __syncthreads();
    const float inv_denom = 1.f / s_denom;

    // ---- loop3: weighted accumulation (x re-read, L2-hot) ----
    float2 acc2[NSLOT];
    #pragma unroll
    for (int i = 0; i < NSLOT; i++) acc2[i] = make_float2(0.f, 0.f);

    for (int s = start + wid; s < end; s += 8) {
        const float w = expf(g_logit[s] - bagmax) * inv_denom;
        const float2* xr = x2 + (size_t)s * D2;
        #pragma unroll
        for (int i = 0; i < NSLOT; i++) {
            int d = lane + i * 32;
            if (d < D2) {
                float2 a = xr[d];
                acc2[i].x = fmaf(w, a.x, acc2[i].x);
                acc2[i].y = fmaf(w, a.y, acc2[i].y);
            }
        }
    }
    // per-warp partials -> smem
    float2* sp = reinterpret_cast<float2*>(s_partial[wid]);
    #pragma unroll
    for (int i = 0; i < NSLOT; i++) {
        int d = lane + i * 32;
        if (d < D2) sp[d] = acc2[i];
    }
    __syncthreads();
    // reduce 8 partials -> bag_repre
    for (int d = tid; d < DD; d += 256) {
        float t = 0.f;
        #pragma unroll
        for (int w2 = 0; w2 < 8; w2++) t += s_partial[w2][d];
        g_bag[(size_t)b * DD + d] = t;
    }
}

// ---------------------------------------------------------------------------
// Kernel 2: logits[b,c] = bag_repre[b,:] · rel[c,:] + bias[c]
// 16 bags per block in smem; warp-per-class with shuffle reduction.
// ---------------------------------------------------------------------------
__global__ void __launch_bounds__(256)
out_gemm_kernel(const float* __restrict__ rel,
                const float* __restrict__ bias,
                float* __restrict__ out) {
    __shared__ float s_bag[16][DD];      // 44160 B

    const int b0   = blockIdx.x * 16;
    const int tid  = threadIdx.x;
    const int wid  = tid >> 5;
    const int lane = tid & 31;

    // load bag tile (contiguous)
    const float* src = g_bag + (size_t)b0 * DD;
    float* dst = &s_bag[0][0];
    for (int i = tid; i < 16 * DD; i += 256) dst[i] = src[i];
    __syncthreads();

    const float2* __restrict__ rel2 = reinterpret_cast<const float2*>(rel);

    for (int c = wid; c < CC; c += 8) {
        const float2* r2 = rel2 + (size_t)c * D2;
        float acc[16];
        #pragma unroll
        for (int k = 0; k < 16; k++) acc[k] = 0.f;

        for (int d = lane; d < D2; d += 32) {
            float2 rv = r2[d];
            #pragma unroll
            for (int k = 0; k < 16; k++) {
                float2 bv = reinterpret_cast<const float2*>(s_bag[k])[d];
                acc[k] = fmaf(bv.x, rv.x, fmaf(bv.y, rv.y, acc[k]));
            }
        }
        #pragma unroll
        for (int k = 0; k < 16; k++) {
            #pragma unroll
            for (int off = 16; off; off >>= 1)
                acc[k] += __shfl_xor_sync(0xFFFFFFFFu, acc[k], off);
        }
        if (lane < 16)
            out[(size_t)(b0 + lane) * CC + c] = acc[lane] + bias[c];
    }
}

// ---------------------------------------------------------------------------
// Entry point. Inputs (metadata order):
//   0: x [N,D] f32   1: relation_weight [C,D] f32   2: attention_weight [C,D] f32
//   3: bias [C] f32  4: attention_query [N] i32     5: scope [B+1] i32
// Output: logits [B,C] f32
// ---------------------------------------------------------------------------
extern "C" void kernel_launch(void* const* d_in, const int* in_sizes, int n_in,
                              void* d_out, int out_size) {
    const float* x    = (const float*)d_in[0];
    const float* rel  = (const float*)d_in[1];
    const float* att  = (const float*)d_in[2];
    const float* bias = (const float*)d_in[3];
    const int*   q    = (const int*)d_in[4];
    const int*   scp  = (const int*)d_in[5];
    float* out = (float*)d_out;

    prod_kernel<<<(CC * DD + 255) / 256, 256>>>(rel, att);
    bag_attn_kernel<<<BB, 256>>>(x, q, scp);
    out_gemm_kernel<<<BB / 16, 256>>>(rel, bias, out);
    (void)in_sizes; (void)n_in; (void)out_size;
}